// round 3
// baseline (speedup 1.0000x reference)
#include <cuda_runtime.h>
#include <cuda_bf16.h>

#define NN   50000
#define NE   800000
#define FIN  128
#define FH   64
#define FOUT 64
#define KC   1024

// ---------------- scratch (device globals; no allocation) ----------------
__device__ __align__(16) float g_h[NN * FH];      // x @ W1
__device__ __align__(16) float g_agg[NN * FH];    // neighbor aggregation
__device__ __align__(16) float g_x1[NN * FH];     // relu(gcn1)
__device__ __align__(16) float g_deg[NN];
__device__ float g_dinv[NN];
__device__ __align__(16) float g_psum[KC * FH];   // cluster sums
__device__ __align__(16) float g_pcnt[KC];
__device__ __align__(16) float g_A[KC * KC];      // pooled adjacency (0/1)
__device__ __align__(16) float g_degp[KC];
__device__ __align__(16) float g_hps[KC * FH];    // dinv_p[s] * (x_p @ W2)
__device__ __align__(16) float g_xp2[KC * FOUT];  // pooled conv output

// ---------------- helpers ----------------
__device__ __forceinline__ float2 unpack2(unsigned long long v) {
    float2 f;
    asm("mov.b64 {%0, %1}, %2;" : "=f"(f.x), "=f"(f.y) : "l"(v));
    return f;
}
__device__ __forceinline__ void ffma2(unsigned long long& d, unsigned long long a,
                                      unsigned long long b) {
    asm("fma.rn.f32x2 %0, %1, %2, %0;" : "+l"(d) : "l"(a), "l"(b));
}
__device__ __forceinline__ void red4(float* p, float4 v) {
    asm volatile("red.global.add.v4.f32 [%0], {%1,%2,%3,%4};"
                 :: "l"(p), "f"(v.x), "f"(v.y), "f"(v.z), "f"(v.w) : "memory");
}

// ---------------- kernels ----------------
__global__ void zero_all_kernel() {
    int i = blockIdx.x * blockDim.x + threadIdx.x;
    float4 z = make_float4(0.f, 0.f, 0.f, 0.f);
    if (i < NN * FH / 4) ((float4*)g_agg)[i] = z;
    if (i < KC * KC / 4) ((float4*)g_A)[i] = z;
    if (i < KC * FH / 4) ((float4*)g_psum)[i] = z;
    if (i < NN / 4)      ((float4*)g_deg)[i] = z;
    if (i < KC / 4) { ((float4*)g_pcnt)[i] = z; ((float4*)g_degp)[i] = z; }
}

// fused: degree atomics + pooled adjacency stores (one edge-list pass)
__global__ void edge_pre_kernel(const int* __restrict__ src, const int* __restrict__ dst,
                                const int* __restrict__ cluster) {
    int e = blockIdx.x * blockDim.x + threadIdx.x;
    if (e < NE) {
        int s = src[e], d = dst[e];
        atomicAdd(&g_deg[d], 1.0f);
        g_A[cluster[s] * KC + cluster[d]] = 1.0f;   // idempotent race
    }
}

__global__ void dinv_kernel() {
    int i = blockIdx.x * blockDim.x + threadIdx.x;
    if (i < NN) g_dinv[i] = rsqrtf(g_deg[i] + 1.0f);
}

// h = x @ W1 : [50000,128]@[128,64]. Warp: 16 rows x 64 cols, k-pair f32x2 accumulation.
// smem: Wt[64][132] transposed W1 + per-warp x stage [16][128]. fma-bound design.
#define W1_STRIDE 132
__global__ void __launch_bounds__(256, 2) gemm1_kernel(const float* __restrict__ x,
                                                       const float* __restrict__ W1) {
    extern __shared__ float smem[];
    float* Wt = smem;                       // 64*132 floats
    float* xs = smem + 64 * W1_STRIDE;      // 8*16*128 floats

    // stage W1 transposed: Wt[col][k]
    for (int i = threadIdx.x; i < FIN * FH; i += 256) {
        int k = i >> 6, col = i & 63;
        Wt[col * W1_STRIDE + k] = W1[i];
    }
    __syncthreads();

    int warp = threadIdx.x >> 5, lane = threadIdx.x & 31;
    int hh = lane >> 4, cc = lane & 15;     // row half, col base (cols cc+16*ci)
    float* xw = xs + warp * 16 * FIN;

    const int ntasks = NN / 16;             // 3125 exact
    for (int t = blockIdx.x * 8 + warp; t < ntasks; t += gridDim.x * 8) {
        int row0 = t * 16;
        #pragma unroll 4
        for (int r = 0; r < 16; r++) {
            float4 v = ((const float4*)x)[(size_t)(row0 + r) * 32 + lane];
            ((float4*)(xw + r * FIN))[lane] = v;
        }
        __syncwarp();

        unsigned long long acc[8][4];
        #pragma unroll
        for (int r = 0; r < 8; r++)
            #pragma unroll
            for (int ci = 0; ci < 4; ci++) acc[r][ci] = 0ull;

        #pragma unroll 4
        for (int k4 = 0; k4 < FIN / 4; k4++) {
            int k0 = k4 * 4;
            ulonglong2 w[4];
            #pragma unroll
            for (int ci = 0; ci < 4; ci++)
                w[ci] = *(const ulonglong2*)(Wt + (cc + 16 * ci) * W1_STRIDE + k0);
            #pragma unroll
            for (int r = 0; r < 8; r++) {
                ulonglong2 xv = *(const ulonglong2*)(xw + (hh * 8 + r) * FIN + k0);
                #pragma unroll
                for (int ci = 0; ci < 4; ci++) {
                    ffma2(acc[r][ci], xv.x, w[ci].x);
                    ffma2(acc[r][ci], xv.y, w[ci].y);
                }
            }
        }
        #pragma unroll
        for (int r = 0; r < 8; r++) {
            int gr = row0 + hh * 8 + r;
            #pragma unroll
            for (int ci = 0; ci < 4; ci++) {
                float2 f = unpack2(acc[r][ci]);
                g_h[gr * FH + cc + 16 * ci] = f.x + f.y;
            }
        }
        __syncwarp();
    }
}

// agg[dst] += norm * h[src] ; 16 lanes per edge, float4 per lane, vector red.
__global__ void edge_agg_kernel(const int* __restrict__ src, const int* __restrict__ dst) {
    int tid = blockIdx.x * blockDim.x + threadIdx.x;
    int e = tid >> 4, q = tid & 15;
    if (e >= NE) return;
    int s = src[e], d = dst[e];
    float norm = g_dinv[s] * g_dinv[d];
    float4 h4 = ((const float4*)g_h)[s * 16 + q];
    float4 v = make_float4(h4.x * norm, h4.y * norm, h4.z * norm, h4.w * norm);
    red4(&g_agg[d * FH + q * 4], v);
}

// x1 = relu(agg + dinv^2*h + b1) ; fused cluster-pool scatter.
__global__ void x1_pool_kernel(const int* __restrict__ cluster, const float* __restrict__ b1) {
    int tid = blockIdx.x * blockDim.x + threadIdx.x;
    int n = tid >> 4, q = tid & 15;
    if (n >= NN) return;
    float di = g_dinv[n];
    float selfw = di * di;
    float4 a  = ((const float4*)g_agg)[n * 16 + q];
    float4 h4 = ((const float4*)g_h)[n * 16 + q];
    float4 b  = ((const float4*)b1)[q];
    float4 v;
    v.x = fmaxf(a.x + selfw * h4.x + b.x, 0.f);
    v.y = fmaxf(a.y + selfw * h4.y + b.y, 0.f);
    v.z = fmaxf(a.z + selfw * h4.z + b.z, 0.f);
    v.w = fmaxf(a.w + selfw * h4.w + b.w, 0.f);
    ((float4*)g_x1)[n * 16 + q] = v;
    int c = cluster[n];
    red4(&g_psum[c * FH + q * 4], v);
    if (q == 0) atomicAdd(&g_pcnt[c], 1.0f);
}

__global__ void a_diag_kernel() {
    int t = blockIdx.x * blockDim.x + threadIdx.x;
    if (t < KC) g_A[t * KC + t] = 1.0f;   // A*(1-I)+I => diag exactly 1
}

// deg_p[t] = column sums of A_hat
__global__ void degp_kernel() {
    int t = blockIdx.x * 256 + threadIdx.x;   // blockIdx.x in 0..3
    int s0 = blockIdx.y * 64;
    float sum = 0.f;
    #pragma unroll 8
    for (int i = 0; i < 64; i++) sum += g_A[(s0 + i) * KC + t];
    atomicAdd(&g_degp[t], sum);
}

// x_p = psum/cnt ; hps = dinv_p[k] * (x_p @ W2)
__global__ void hp_kernel(const float* __restrict__ W2) {
    __shared__ float xp[FH];
    int k = blockIdx.x, f = threadIdx.x;    // 64 threads
    float cnt = fmaxf(g_pcnt[k], 1.0f);
    xp[f] = g_psum[k * FH + f] / cnt;
    __syncthreads();
    float acc = 0.f;
    #pragma unroll
    for (int j = 0; j < FH; j++) acc += xp[j] * W2[j * FOUT + f];
    g_hps[k * FH + f] = acc * rsqrtf(g_degp[k]);
}

// x_p2[t,f] = dinv_p[t] * sum_s A_hat[s,t]*hps[s,f] + b2[f]
__global__ void __launch_bounds__(256) xp2_kernel(const float* __restrict__ b2) {
    __shared__ float As[64][8];
    __shared__ float Hs[64][FH];
    int t0 = blockIdx.x * 8;
    int f = threadIdx.x & 63, g = threadIdx.x >> 6;
    float acc[2] = {0.f, 0.f};
    for (int s0 = 0; s0 < KC; s0 += 64) {
        __syncthreads();
        for (int i = threadIdx.x; i < 64 * 8; i += 256) {
            int si = i >> 3, tj = i & 7;
            As[si][tj] = g_A[(s0 + si) * KC + t0 + tj];
        }
        for (int i = threadIdx.x; i < 64 * 64; i += 256)
            Hs[i >> 6][i & 63] = g_hps[(s0 + (i >> 6)) * FH + (i & 63)];
        __syncthreads();
        #pragma unroll 4
        for (int i = 0; i < 64; i++) {
            float hv = Hs[i][f];
            #pragma unroll
            for (int r = 0; r < 2; r++) acc[r] += As[i][g * 2 + r] * hv;
        }
    }
    float bb = b2[f];
    #pragma unroll
    for (int r = 0; r < 2; r++) {
        int t = t0 + g * 2 + r;
        g_xp2[t * FOUT + f] = rsqrtf(g_degp[t]) * acc[r] + bb;
    }
}

// out = x_p2[cluster] + relu(alpha) * (x1 @ W_skip + b_skip)
// Same register-tiled structure as gemm1, K=64.
#define WS_STRIDE 68
__global__ void __launch_bounds__(256, 2) final_kernel(const int* __restrict__ cluster,
                                                       const float* __restrict__ Wskip,
                                                       const float* __restrict__ bskip,
                                                       const float* __restrict__ alpha,
                                                       float* __restrict__ out) {
    extern __shared__ float smem[];
    float* Wt = smem;                      // 64*68 floats
    float* xs = smem + 64 * WS_STRIDE;     // 8*16*64 floats

    for (int i = threadIdx.x; i < FH * FOUT; i += 256) {
        int k = i >> 6, col = i & 63;
        Wt[col * WS_STRIDE + k] = Wskip[i];
    }
    __syncthreads();

    float ral = fmaxf(alpha[0], 0.f);
    int warp = threadIdx.x >> 5, lane = threadIdx.x & 31;
    int hh = lane >> 4, cc = lane & 15;
    float* xw = xs + warp * 16 * FH;
    float bb[4];
    #pragma unroll
    for (int ci = 0; ci < 4; ci++) bb[ci] = bskip[cc + 16 * ci];

    const int ntasks = NN / 16;            // 3125 exact
    for (int t = blockIdx.x * 8 + warp; t < ntasks; t += gridDim.x * 8) {
        int row0 = t * 16;
        #pragma unroll 4
        for (int rr = 0; rr < 16; rr += 2) {
            int r = rr + (lane >> 4);
            float4 v = ((const float4*)g_x1)[(size_t)(row0 + r) * 16 + (lane & 15)];
            ((float4*)(xw + r * FH))[lane & 15] = v;
        }
        __syncwarp();

        unsigned long long acc[8][4];
        #pragma unroll
        for (int r = 0; r < 8; r++)
            #pragma unroll
            for (int ci = 0; ci < 4; ci++) acc[r][ci] = 0ull;

        #pragma unroll 4
        for (int k4 = 0; k4 < FH / 4; k4++) {
            int k0 = k4 * 4;
            ulonglong2 w[4];
            #pragma unroll
            for (int ci = 0; ci < 4; ci++)
                w[ci] = *(const ulonglong2*)(Wt + (cc + 16 * ci) * WS_STRIDE + k0);
            #pragma unroll
            for (int r = 0; r < 8; r++) {
                ulonglong2 xv = *(const ulonglong2*)(xw + (hh * 8 + r) * FH + k0);
                #pragma unroll
                for (int ci = 0; ci < 4; ci++) {
                    ffma2(acc[r][ci], xv.x, w[ci].x);
                    ffma2(acc[r][ci], xv.y, w[ci].y);
                }
            }
        }
        #pragma unroll
        for (int r = 0; r < 8; r++) {
            int gr = row0 + hh * 8 + r;
            int cl = cluster[gr];
            #pragma unroll
            for (int ci = 0; ci < 4; ci++) {
                float2 f = unpack2(acc[r][ci]);
                int col = cc + 16 * ci;
                out[gr * FOUT + col] =
                    g_xp2[cl * FOUT + col] + ral * (f.x + f.y + bb[ci]);
            }
        }
        __syncwarp();
    }
}

// ---------------- launch ----------------
extern "C" void kernel_launch(void* const* d_in, const int* in_sizes, int n_in,
                              void* d_out, int out_size) {
    const float* x       = (const float*)d_in[0];
    const int*   ei      = (const int*)d_in[1];
    const int*   src     = ei;
    const int*   dst     = ei + NE;
    const int*   cluster = (const int*)d_in[2];
    const float* W1      = (const float*)d_in[3];
    const float* b1      = (const float*)d_in[4];
    const float* W2      = (const float*)d_in[5];
    const float* b2      = (const float*)d_in[6];
    const float* Wsk     = (const float*)d_in[7];
    const float* bsk     = (const float*)d_in[8];
    const float* alpha   = (const float*)d_in[9];
    float* out = (float*)d_out;

    const int SMEM1 = (64 * W1_STRIDE + 8 * 16 * FIN) * 4;   // 99,328 B
    const int SMEM2 = (64 * WS_STRIDE + 8 * 16 * FH) * 4;    // 50,176 B
    cudaFuncSetAttribute(gemm1_kernel, cudaFuncAttributeMaxDynamicSharedMemorySize, SMEM1);
    cudaFuncSetAttribute(final_kernel, cudaFuncAttributeMaxDynamicSharedMemorySize, SMEM2);

    zero_all_kernel<<<(NN * FH / 4 + 255) / 256, 256>>>();
    edge_pre_kernel<<<(NE + 255) / 256, 256>>>(src, dst, cluster);
    dinv_kernel<<<(NN + 255) / 256, 256>>>();
    gemm1_kernel<<<296, 256, SMEM1>>>(x, W1);
    edge_agg_kernel<<<(NE * 16) / 256, 256>>>(src, dst);
    x1_pool_kernel<<<(NN * 16 + 255) / 256, 256>>>(cluster, b1);
    a_diag_kernel<<<(KC + 255) / 256, 256>>>();
    degp_kernel<<<dim3(4, 16), 256>>>();
    hp_kernel<<<KC, 64>>>(W2);
    xp2_kernel<<<KC / 8, 256>>>(b2);
    final_kernel<<<296, 256, SMEM2>>>(cluster, Wsk, bsk, alpha, out);
}

// round 4
// speedup vs baseline: 1.3780x; 1.3780x over previous
#include <cuda_runtime.h>
#include <cuda_bf16.h>

#define NN   50000
#define NE   800000
#define FIN  128
#define FH   64
#define FOUT 64
#define KC   1024

typedef unsigned long long ull;

// ---------------- scratch (device globals; no allocation) ----------------
__device__ __align__(16) float g_h[NN * FH];      // x @ W1
__device__ __align__(16) float g_agg[NN * FH];    // neighbor aggregation
__device__ __align__(16) float g_x1[NN * FH];     // relu(gcn1)
__device__ __align__(16) float g_deg[NN];
__device__ float g_dinv[NN];
__device__ __align__(16) float g_psum[KC * FH];   // cluster sums
__device__ __align__(16) float g_pcnt[KC];
__device__ __align__(16) float g_A[KC * KC];      // pooled adjacency (0/1)
__device__ __align__(16) float g_degp[KC];
__device__ __align__(16) float g_hps[KC * FH];    // dinv_p[s] * (x_p @ W2)
__device__ __align__(16) float g_xp2[KC * FOUT];  // pooled conv output

// ---------------- helpers ----------------
__device__ __forceinline__ ull pack2(float x, float y) {
    ull r;
    asm("mov.b64 %0, {%1, %2};" : "=l"(r) : "f"(x), "f"(y));
    return r;
}
__device__ __forceinline__ float2 unpack2(ull v) {
    float2 f;
    asm("mov.b64 {%0, %1}, %2;" : "=f"(f.x), "=f"(f.y) : "l"(v));
    return f;
}
__device__ __forceinline__ void ffma2(ull& d, ull a, ull b) {
    asm("fma.rn.f32x2 %0, %1, %2, %0;" : "+l"(d) : "l"(a), "l"(b));
}
__device__ __forceinline__ void red4(float* p, float4 v) {
    asm volatile("red.global.add.v4.f32 [%0], {%1,%2,%3,%4};"
                 :: "l"(p), "f"(v.x), "f"(v.y), "f"(v.z), "f"(v.w) : "memory");
}
__device__ __forceinline__ float hsum2(ull v) {
    float2 f = unpack2(v);
    return f.x + f.y;
}

// ---------------- small kernels ----------------
__global__ void zero_all_kernel() {
    int i = blockIdx.x * blockDim.x + threadIdx.x;
    float4 z = make_float4(0.f, 0.f, 0.f, 0.f);
    if (i < NN * FH / 4) ((float4*)g_agg)[i] = z;
    if (i < KC * KC / 4) ((float4*)g_A)[i] = z;
    if (i < KC * FH / 4) ((float4*)g_psum)[i] = z;
    if (i < NN / 4)      ((float4*)g_deg)[i] = z;
    if (i < KC / 4) { ((float4*)g_pcnt)[i] = z; ((float4*)g_degp)[i] = z; }
}

// fused: degree atomics + pooled adjacency stores (one edge-list pass)
__global__ void edge_pre_kernel(const int* __restrict__ src, const int* __restrict__ dst,
                                const int* __restrict__ cluster) {
    int e = blockIdx.x * blockDim.x + threadIdx.x;
    if (e < NE) {
        int s = src[e], d = dst[e];
        atomicAdd(&g_deg[d], 1.0f);
        g_A[cluster[s] * KC + cluster[d]] = 1.0f;   // idempotent race
    }
}

__global__ void dinv_kernel() {
    int i = blockIdx.x * blockDim.x + threadIdx.x;
    if (i < NN) g_dinv[i] = rsqrtf(g_deg[i] + 1.0f);
}

// ---------------- gemm1: h = x @ W1  [50000,128]@[128,64] ----------------
// SIMT tile: block 64 rows x 64 cols, warp 32x16, thread 4x4.
// w2[kpair][col] = packed (W[2kp][c], W[2kp+1][c]); x staged row-major.
// Per 4-k: 8 LDS.128 + 32 FFMA2 (80% fma mix), ~76 regs, 3 CTAs/SM.
#define SX1 132   // xs row stride (floats): phase diff 2112B = 64 mod 128 -> conflict-free
#define SW1 66    // w2 row stride (ull)
__global__ void __launch_bounds__(256, 3) gemm1_kernel(const float* __restrict__ x,
                                                       const float* __restrict__ W1) {
    extern __shared__ float smem[];
    float* xs = smem;                        // 64*132 floats = 33792 B
    ull*   w2 = (ull*)(smem + 64 * SX1);     // 64*66 ull    = 33792 B

    int tid = threadIdx.x;
    int row0 = blockIdx.x * 64;

    // stage w2: kpairs along k
    for (int i = tid; i < 64 * 64; i += 256) {
        int kp = i >> 6, c = i & 63;
        w2[kp * SW1 + c] = pack2(W1[(2 * kp) * FH + c], W1[(2 * kp + 1) * FH + c]);
    }
    // stage xs (guarded)
    for (int i = tid; i < 64 * 32; i += 256) {
        int r = i >> 5, k4 = i & 31;
        int gr = row0 + r;
        float4 v = make_float4(0.f, 0.f, 0.f, 0.f);
        if (gr < NN) v = ((const float4*)x)[(size_t)gr * 32 + k4];
        *(float4*)&xs[r * SX1 + k4 * 4] = v;
    }
    __syncthreads();

    int lane = tid & 31, warp = tid >> 5;
    int rg = lane >> 2, cg = lane & 3;       // 8 rowgroups x 4 colgroups
    int wr = warp >> 2, wc = warp & 3;       // 2 row-bands x 4 col-bands
    int rbase = wr * 32 + rg * 4;
    int col0  = wc * 16 + cg * 4;

    ull acc[4][4];
    #pragma unroll
    for (int r = 0; r < 4; r++)
        #pragma unroll
        for (int c = 0; c < 4; c++) acc[r][c] = 0ull;

    #pragma unroll 4
    for (int it = 0; it < 32; it++) {
        int k0 = it * 4;
        ulonglong2 xv[4];
        #pragma unroll
        for (int r = 0; r < 4; r++)
            xv[r] = *(const ulonglong2*)&xs[(rbase + r) * SX1 + k0];
        const ull* wp = w2 + (2 * it) * SW1 + col0;
        ulonglong2 wa = *(const ulonglong2*)wp;            // kp0: cols c0,c0+1
        ulonglong2 wb = *(const ulonglong2*)(wp + 2);      // kp0: cols c0+2,c0+3
        ulonglong2 wc2 = *(const ulonglong2*)(wp + SW1);   // kp1: cols c0,c0+1
        ulonglong2 wd = *(const ulonglong2*)(wp + SW1 + 2);
        #pragma unroll
        for (int r = 0; r < 4; r++) {
            ffma2(acc[r][0], xv[r].x, wa.x);  ffma2(acc[r][0], xv[r].y, wc2.x);
            ffma2(acc[r][1], xv[r].x, wa.y);  ffma2(acc[r][1], xv[r].y, wc2.y);
            ffma2(acc[r][2], xv[r].x, wb.x);  ffma2(acc[r][2], xv[r].y, wd.x);
            ffma2(acc[r][3], xv[r].x, wb.y);  ffma2(acc[r][3], xv[r].y, wd.y);
        }
    }

    #pragma unroll
    for (int r = 0; r < 4; r++) {
        int gr = row0 + rbase + r;
        if (gr < NN) {
            float4 o = make_float4(hsum2(acc[r][0]), hsum2(acc[r][1]),
                                   hsum2(acc[r][2]), hsum2(acc[r][3]));
            *(float4*)&g_h[gr * FH + col0] = o;
        }
    }
}

// agg[dst] += norm * h[src] ; 16 lanes per edge, float4 per lane, vector red.
__global__ void edge_agg_kernel(const int* __restrict__ src, const int* __restrict__ dst) {
    int tid = blockIdx.x * blockDim.x + threadIdx.x;
    int e = tid >> 4, q = tid & 15;
    if (e >= NE) return;
    int s = src[e], d = dst[e];
    float norm = g_dinv[s] * g_dinv[d];
    float4 h4 = ((const float4*)g_h)[s * 16 + q];
    float4 v = make_float4(h4.x * norm, h4.y * norm, h4.z * norm, h4.w * norm);
    red4(&g_agg[d * FH + q * 4], v);
}

// x1 = relu(agg + dinv^2*h + b1) ; fused cluster-pool scatter.
__global__ void x1_pool_kernel(const int* __restrict__ cluster, const float* __restrict__ b1) {
    int tid = blockIdx.x * blockDim.x + threadIdx.x;
    int n = tid >> 4, q = tid & 15;
    if (n >= NN) return;
    float di = g_dinv[n];
    float selfw = di * di;
    float4 a  = ((const float4*)g_agg)[n * 16 + q];
    float4 h4 = ((const float4*)g_h)[n * 16 + q];
    float4 b  = ((const float4*)b1)[q];
    float4 v;
    v.x = fmaxf(a.x + selfw * h4.x + b.x, 0.f);
    v.y = fmaxf(a.y + selfw * h4.y + b.y, 0.f);
    v.z = fmaxf(a.z + selfw * h4.z + b.z, 0.f);
    v.w = fmaxf(a.w + selfw * h4.w + b.w, 0.f);
    ((float4*)g_x1)[n * 16 + q] = v;
    int c = cluster[n];
    red4(&g_psum[c * FH + q * 4], v);
    if (q == 0) atomicAdd(&g_pcnt[c], 1.0f);
}

__global__ void a_diag_kernel() {
    int t = blockIdx.x * blockDim.x + threadIdx.x;
    if (t < KC) g_A[t * KC + t] = 1.0f;   // A*(1-I)+I => diag exactly 1
}

// deg_p[t] = column sums of A_hat
__global__ void degp_kernel() {
    int t = blockIdx.x * 256 + threadIdx.x;
    int s0 = blockIdx.y * 64;
    float sum = 0.f;
    #pragma unroll 8
    for (int i = 0; i < 64; i++) sum += g_A[(s0 + i) * KC + t];
    atomicAdd(&g_degp[t], sum);
}

// x_p = psum/cnt ; hps = dinv_p[k] * (x_p @ W2)
__global__ void hp_kernel(const float* __restrict__ W2) {
    __shared__ float xp[FH];
    int k = blockIdx.x, f = threadIdx.x;
    float cnt = fmaxf(g_pcnt[k], 1.0f);
    xp[f] = g_psum[k * FH + f] / cnt;
    __syncthreads();
    float acc = 0.f;
    #pragma unroll
    for (int j = 0; j < FH; j++) acc += xp[j] * W2[j * FOUT + f];
    g_hps[k * FH + f] = acc * rsqrtf(g_degp[k]);
}

// x_p2[t,f] = dinv_p[t] * sum_s A_hat[s,t]*hps[s,f] + b2[f]
__global__ void __launch_bounds__(256) xp2_kernel(const float* __restrict__ b2) {
    __shared__ float As[64][8];
    __shared__ float Hs[64][FH];
    int t0 = blockIdx.x * 8;
    int f = threadIdx.x & 63, g = threadIdx.x >> 6;
    float acc[2] = {0.f, 0.f};
    for (int s0 = 0; s0 < KC; s0 += 64) {
        __syncthreads();
        for (int i = threadIdx.x; i < 64 * 8; i += 256) {
            int si = i >> 3, tj = i & 7;
            As[si][tj] = g_A[(s0 + si) * KC + t0 + tj];
        }
        for (int i = threadIdx.x; i < 64 * 64; i += 256)
            Hs[i >> 6][i & 63] = g_hps[(s0 + (i >> 6)) * FH + (i & 63)];
        __syncthreads();
        #pragma unroll 4
        for (int i = 0; i < 64; i++) {
            float hv = Hs[i][f];
            #pragma unroll
            for (int r = 0; r < 2; r++) acc[r] += As[i][g * 2 + r] * hv;
        }
    }
    float bb = b2[f];
    #pragma unroll
    for (int r = 0; r < 2; r++) {
        int t = t0 + g * 2 + r;
        g_xp2[t * FOUT + f] = rsqrtf(g_degp[t]) * acc[r] + bb;
    }
}

// ---------------- final: out = xp2[cluster] + relu(alpha)*(x1@Wskip + bskip) ----
// Same SIMT geometry as gemm1, K=64.
#define SXF 68    // xs row stride (floats)
#define SWF 66    // w2 row stride (ull)
__global__ void __launch_bounds__(256, 3) final_kernel(const int* __restrict__ cluster,
                                                       const float* __restrict__ Wskip,
                                                       const float* __restrict__ bskip,
                                                       const float* __restrict__ alpha,
                                                       float* __restrict__ out) {
    extern __shared__ float smem[];
    float* xs = smem;                        // 64*68 floats = 17408 B
    ull*   w2 = (ull*)(smem + 64 * SXF);     // 32*66 ull    = 16896 B

    int tid = threadIdx.x;
    int row0 = blockIdx.x * 64;

    for (int i = tid; i < 32 * 64; i += 256) {
        int kp = i >> 6, c = i & 63;
        w2[kp * SWF + c] = pack2(Wskip[(2 * kp) * FOUT + c], Wskip[(2 * kp + 1) * FOUT + c]);
    }
    for (int i = tid; i < 64 * 16; i += 256) {
        int r = i >> 4, k4 = i & 15;
        int gr = row0 + r;
        float4 v = make_float4(0.f, 0.f, 0.f, 0.f);
        if (gr < NN) v = ((const float4*)g_x1)[(size_t)gr * 16 + k4];
        *(float4*)&xs[r * SXF + k4 * 4] = v;
    }
    __syncthreads();

    int lane = tid & 31, warp = tid >> 5;
    int rg = lane >> 2, cg = lane & 3;
    int wr = warp >> 2, wc = warp & 3;
    int rbase = wr * 32 + rg * 4;
    int col0  = wc * 16 + cg * 4;

    float ral = fmaxf(alpha[0], 0.f);
    float4 bb = *(const float4*)&bskip[col0];

    ull acc[4][4];
    #pragma unroll
    for (int r = 0; r < 4; r++)
        #pragma unroll
        for (int c = 0; c < 4; c++) acc[r][c] = 0ull;

    #pragma unroll 4
    for (int it = 0; it < 16; it++) {
        int k0 = it * 4;
        ulonglong2 xv[4];
        #pragma unroll
        for (int r = 0; r < 4; r++)
            xv[r] = *(const ulonglong2*)&xs[(rbase + r) * SXF + k0];
        const ull* wp = w2 + (2 * it) * SWF + col0;
        ulonglong2 wa = *(const ulonglong2*)wp;
        ulonglong2 wb = *(const ulonglong2*)(wp + 2);
        ulonglong2 wc2 = *(const ulonglong2*)(wp + SWF);
        ulonglong2 wd = *(const ulonglong2*)(wp + SWF + 2);
        #pragma unroll
        for (int r = 0; r < 4; r++) {
            ffma2(acc[r][0], xv[r].x, wa.x);  ffma2(acc[r][0], xv[r].y, wc2.x);
            ffma2(acc[r][1], xv[r].x, wa.y);  ffma2(acc[r][1], xv[r].y, wc2.y);
            ffma2(acc[r][2], xv[r].x, wb.x);  ffma2(acc[r][2], xv[r].y, wd.x);
            ffma2(acc[r][3], xv[r].x, wb.y);  ffma2(acc[r][3], xv[r].y, wd.y);
        }
    }

    #pragma unroll
    for (int r = 0; r < 4; r++) {
        int gr = row0 + rbase + r;
        if (gr < NN) {
            int cl = cluster[gr];
            float4 up = *(const float4*)&g_xp2[cl * FOUT + col0];
            float4 o;
            o.x = up.x + ral * (hsum2(acc[r][0]) + bb.x);
            o.y = up.y + ral * (hsum2(acc[r][1]) + bb.y);
            o.z = up.z + ral * (hsum2(acc[r][2]) + bb.z);
            o.w = up.w + ral * (hsum2(acc[r][3]) + bb.w);
            *(float4*)&out[(size_t)gr * FOUT + col0] = o;
        }
    }
}

// ---------------- launch ----------------
extern "C" void kernel_launch(void* const* d_in, const int* in_sizes, int n_in,
                              void* d_out, int out_size) {
    const float* x       = (const float*)d_in[0];
    const int*   ei      = (const int*)d_in[1];
    const int*   src     = ei;
    const int*   dst     = ei + NE;
    const int*   cluster = (const int*)d_in[2];
    const float* W1      = (const float*)d_in[3];
    const float* b1      = (const float*)d_in[4];
    const float* W2      = (const float*)d_in[5];
    const float* b2      = (const float*)d_in[6];
    const float* Wsk     = (const float*)d_in[7];
    const float* bsk     = (const float*)d_in[8];
    const float* alpha   = (const float*)d_in[9];
    float* out = (float*)d_out;

    const int SMEM1 = 64 * SX1 * 4 + 64 * SW1 * 8;   // 33792 + 33792 = 67584 B
    const int SMEM2 = 64 * SXF * 4 + 32 * SWF * 8;   // 17408 + 16896 = 34304 B
    cudaFuncSetAttribute(gemm1_kernel, cudaFuncAttributeMaxDynamicSharedMemorySize, SMEM1);
    cudaFuncSetAttribute(final_kernel, cudaFuncAttributeMaxDynamicSharedMemorySize, SMEM2);

    const int NB = (NN + 63) / 64;   // 782

    zero_all_kernel<<<(NN * FH / 4 + 255) / 256, 256>>>();
    edge_pre_kernel<<<(NE + 255) / 256, 256>>>(src, dst, cluster);
    dinv_kernel<<<(NN + 255) / 256, 256>>>();
    gemm1_kernel<<<NB, 256, SMEM1>>>(x, W1);
    edge_agg_kernel<<<(NE * 16) / 256, 256>>>(src, dst);
    x1_pool_kernel<<<(NN * 16 + 255) / 256, 256>>>(cluster, b1);
    a_diag_kernel<<<(KC + 255) / 256, 256>>>();
    degp_kernel<<<dim3(4, 16), 256>>>();
    hp_kernel<<<KC, 64>>>(W2);
    xp2_kernel<<<KC / 8, 256>>>(b2);
    final_kernel<<<NB, 256, SMEM2>>>(cluster, Wsk, bsk, alpha, out);
}